// round 12
// baseline (speedup 1.0000x reference)
#include <cuda_runtime.h>
#include <cuda_bf16.h>
#include <cuda_fp16.h>
#include <math.h>

// Fixed shapes: seq (256,40) int32, sim (512,512) f32, pers (512,512,512) f32,
// weights (2,) f32, output scalar f32.
constexpr int V = 512;
constexpr int B = 256;
constexpr int L = 40;
constexpr int ROWS = B * (L - 1);        // 9984
constexpr int WARPS_PER_BLOCK = 8;       // 256 threads, 1 row per warp
constexpr int NBLOCKS = ROWS / WARPS_PER_BLOCK;  // 1248

constexpr float LOG2E = 1.44269504088896340736f;
constexpr float LN2   = 0.69314718055994530942f;
// nll0 = B * ln(V)
constexpr float NLL0  = 256.0f * 6.2383246250395075f;

// Packed cross-CTA accumulator: bits [0:44) fixed-point sum (2^-20 units,
// all contributions >= 0), bits [44:64) CTA arrival count. One atomic per
// CTA; the returned old value is authoritative (no fence needed).
__device__ unsigned long long g_packed = 0ull;
constexpr int  CNT_SHIFT = 44;
constexpr unsigned long long SUM_MASK = (1ull << CNT_SHIFT) - 1ull;
constexpr float FP_SCALE  = 1048576.0f;        // 2^20
constexpr float FP_INV    = 1.0f / 1048576.0f;

// 32-byte global load with L2 evict_last (sm_103a ptxas requires .v8.b32).
struct F8 { float v[8]; };
__device__ __forceinline__ F8 ldg_el8(const float* p) {
    F8 r;
    asm("ld.global.nc.L2::evict_last.v8.b32 {%0,%1,%2,%3,%4,%5,%6,%7}, [%8];"
        : "=f"(r.v[0]), "=f"(r.v[1]), "=f"(r.v[2]), "=f"(r.v[3]),
          "=f"(r.v[4]), "=f"(r.v[5]), "=f"(r.v[6]), "=f"(r.v[7])
        : "l"(p));
    return r;
}

__global__ __launch_bounds__(256)
void nll_kernel(const int* __restrict__ seq,
                const float* __restrict__ sim,
                const float* __restrict__ pers,
                const float* __restrict__ w,
                float* __restrict__ out) {
    const int warp = threadIdx.x >> 5;
    const int lane = threadIdx.x & 31;
    const int row  = blockIdx.x * WARPS_PER_BLOCK + warp;   // 0..ROWS-1
    const int b = row / (L - 1);
    const int t = row % (L - 1);
    const int base = b * L + t;

    const int prev = seq[base];
    const int tgt  = seq[base + 1];
    // fold log2(e) into the weights: y = log2(e) * (w0*s + w1*p)
    const float w0l = w[0] * LOG2E;
    const float w1l = w[1] * LOG2E;

    // ---- DRAM stream first: 2x v8 (64 B) per lane from the random pers row ----
    // t==0 rows read a clamped valid row with weight 0 (branchless).
    const bool hasP = (t >= 1);
    const int  p0   = hasP ? seq[base - 1] : prev;
    const float w1r = hasP ? w1l : 0.f;
    const float* prow = pers + ((size_t)p0 * V + (size_t)prev) * V;
    F8 pv[2];
    #pragma unroll
    for (int j = 0; j < 2; j++) pv[j] = ldg_el8(prow + (lane + 32 * j) * 8);

    // ---- L2-resident sim row ----
    const float* srow = sim + (size_t)prev * V;
    F8 sv[2];
    #pragma unroll
    for (int j = 0; j < 2; j++) sv[j] = ldg_el8(srow + (lane + 32 * j) * 8);

    const int tj = tgt >> 8;            // which 32-lane chunk
    const int tl = (tgt >> 3) & 31;     // owning lane
    const int tc = tgt & 7;             // component within F8

    // ---- sum of 2^y via packed f16x2 ex2 ----
    float se = 0.f;     // f32 accumulator
    float tv = 0.f;     // target y (log2 domain)
    #pragma unroll
    for (int j = 0; j < 2; j++) {
        float y[8];
        #pragma unroll
        for (int c = 0; c < 8; c++)
            y[c] = fmaf(w1r, pv[j].v[c], w0l * sv[j].v[c]);

        #pragma unroll
        for (int c = 0; c < 8; c += 4) {
            __half2 ea = h2exp2(__floats2half2_rn(y[c],     y[c + 1]));
            __half2 eb = h2exp2(__floats2half2_rn(y[c + 2], y[c + 3]));
            __half2 hs = __hadd2(ea, eb);
            float2 f = __half22float2(hs);
            se += f.x + f.y;
        }
        if (j == tj) tv = y[tc];
    }

    #pragma unroll
    for (int o = 16; o; o >>= 1) se += __shfl_xor_sync(0xffffffffu, se, o);
    tv = __shfl_sync(0xffffffffu, tv, tl);

    // per-row nll = ln2 * (log2(sum 2^y) - y_tgt)  (>= 0 always)
    __shared__ float sh[WARPS_PER_BLOCK];
    if (lane == 0) sh[warp] = LN2 * (__log2f(se) - tv);
    __syncthreads();

    if (threadIdx.x == 0) {
        float acc = 0.f;
        #pragma unroll
        for (int i = 0; i < WARPS_PER_BLOCK; i++) acc += sh[i];

        // single packed atomic: fixed-point sum + arrival count, fence-free
        const unsigned long long term =
            (unsigned long long)llrintf(acc * FP_SCALE) | (1ull << CNT_SHIFT);
        const unsigned long long old = atomicAdd(&g_packed, term);
        if ((old >> CNT_SHIFT) == (unsigned long long)(NBLOCKS - 1)) {
            const unsigned long long total = (old + term) & SUM_MASK;
            out[0] = (float)total * FP_INV + NLL0;
            atomicExch(&g_packed, 0ull);   // reset for next graph replay
        }
    }
}

extern "C" void kernel_launch(void* const* d_in, const int* in_sizes, int n_in,
                              void* d_out, int out_size) {
    const int*   seq  = (const int*)  d_in[0];
    const float* sim  = (const float*)d_in[1];
    const float* pers = (const float*)d_in[2];
    const float* w    = (const float*)d_in[3];
    float* out = (float*)d_out;

    nll_kernel<<<NBLOCKS, 256>>>(seq, sim, pers, w, out);
}

// round 13
// speedup vs baseline: 1.1792x; 1.1792x over previous
#include <cuda_runtime.h>
#include <cuda_bf16.h>
#include <cuda_fp16.h>
#include <math.h>

// Fixed shapes: seq (256,40) int32, sim (512,512) f32, pers (512,512,512) f32,
// weights (2,) f32, output scalar f32.
constexpr int V = 512;
constexpr int B = 256;
constexpr int L = 40;
constexpr int ROWS = B * (L - 1);        // 9984
constexpr int WARPS_PER_BLOCK = 8;       // 256 threads, 1 row per warp
constexpr int NBLOCKS = ROWS / WARPS_PER_BLOCK;  // 1248

constexpr float LOG2E = 1.44269504088896340736f;
constexpr float LN2   = 0.69314718055994530942f;

// 32-byte global load with L2 evict_last (sm_103a ptxas requires .v8.b32).
struct F8 { float v[8]; };
__device__ __forceinline__ F8 ldg_el8(const float* p) {
    F8 r;
    asm("ld.global.nc.L2::evict_last.v8.b32 {%0,%1,%2,%3,%4,%5,%6,%7}, [%8];"
        : "=f"(r.v[0]), "=f"(r.v[1]), "=f"(r.v[2]), "=f"(r.v[3]),
          "=f"(r.v[4]), "=f"(r.v[5]), "=f"(r.v[6]), "=f"(r.v[7])
        : "l"(p));
    return r;
}

__global__ void init_out_kernel(float* out) {
    // Order against the PREVIOUS graph-replay's nll_kernel: all its atomics
    // to out[0] must be visible before we overwrite with nll0.
    cudaGridDependencySynchronize();
    out[0] = (float)B * logf((float)V);  // nll0
    cudaTriggerProgrammaticLaunchCompletion();
}

__global__ __launch_bounds__(256)
void nll_kernel(const int* __restrict__ seq,
                const float* __restrict__ sim,
                const float* __restrict__ pers,
                const float* __restrict__ w,
                float* __restrict__ out) {
    const int warp = threadIdx.x >> 5;
    const int lane = threadIdx.x & 31;
    const int row  = blockIdx.x * WARPS_PER_BLOCK + warp;   // 0..ROWS-1
    const int b = row / (L - 1);
    const int t = row % (L - 1);
    const int base = b * L + t;

    const int prev = seq[base];
    const int tgt  = seq[base + 1];
    // fold log2(e) into the weights: y = log2(e) * (w0*s + w1*p)
    const float w0l = w[0] * LOG2E;
    const float w1l = w[1] * LOG2E;

    // ---- DRAM stream first: 2x v8 (64 B) per lane from the random pers row ----
    // t==0 rows read a clamped valid row with weight 0 (branchless).
    const bool hasP = (t >= 1);
    const int  p0   = hasP ? seq[base - 1] : prev;
    const float w1r = hasP ? w1l : 0.f;
    const float* prow = pers + ((size_t)p0 * V + (size_t)prev) * V;
    F8 pv[2];
    #pragma unroll
    for (int j = 0; j < 2; j++) pv[j] = ldg_el8(prow + (lane + 32 * j) * 8);

    // ---- L2-resident sim row ----
    const float* srow = sim + (size_t)prev * V;
    F8 sv[2];
    #pragma unroll
    for (int j = 0; j < 2; j++) sv[j] = ldg_el8(srow + (lane + 32 * j) * 8);

    const int tj = tgt >> 8;            // which 32-lane chunk
    const int tl = (tgt >> 3) & 31;     // owning lane
    const int tc = tgt & 7;             // component within F8

    // ---- sum of 2^y via packed f16x2 ex2 ----
    float se = 0.f;     // f32 accumulator
    float tv = 0.f;     // target y (log2 domain)
    #pragma unroll
    for (int j = 0; j < 2; j++) {
        float y[8];
        #pragma unroll
        for (int c = 0; c < 8; c++)
            y[c] = fmaf(w1r, pv[j].v[c], w0l * sv[j].v[c]);

        #pragma unroll
        for (int c = 0; c < 8; c += 4) {
            __half2 ea = h2exp2(__floats2half2_rn(y[c],     y[c + 1]));
            __half2 eb = h2exp2(__floats2half2_rn(y[c + 2], y[c + 3]));
            __half2 hs = __hadd2(ea, eb);
            float2 f = __half22float2(hs);
            se += f.x + f.y;
        }
        if (j == tj) tv = y[tc];
    }

    #pragma unroll
    for (int o = 16; o; o >>= 1) se += __shfl_xor_sync(0xffffffffu, se, o);
    tv = __shfl_sync(0xffffffffu, tv, tl);

    // nll = ln2 * (log2(sum 2^y) - y_tgt)
    __shared__ float sh[WARPS_PER_BLOCK];
    if (lane == 0) sh[warp] = LN2 * (__log2f(se) - tv);
    __syncthreads();

    if (threadIdx.x == 0) {
        float acc = 0.f;
        #pragma unroll
        for (int i = 0; i < WARPS_PER_BLOCK; i++) acc += sh[i];
        // PDL: ensure init kernel's out[0] = nll0 store is visible before
        // accumulating. All heavy work above overlapped the init node.
        cudaGridDependencySynchronize();
        atomicAdd(out, acc);
    }
}

extern "C" void kernel_launch(void* const* d_in, const int* in_sizes, int n_in,
                              void* d_out, int out_size) {
    const int*   seq  = (const int*)  d_in[0];
    const float* sim  = (const float*)d_in[1];
    const float* pers = (const float*)d_in[2];
    const float* w    = (const float*)d_in[3];
    float* out = (float*)d_out;

    cudaLaunchAttribute attrs[1];
    attrs[0].id = cudaLaunchAttributeProgrammaticStreamSerialization;
    attrs[0].val.programmaticStreamSerializationAllowed = 1;

    // init node: PSS lets it launch while the PREVIOUS replay's nll_kernel
    // is still draining (its GDS orders the out[0] overwrite).
    cudaLaunchConfig_t cfg0 = {};
    cfg0.gridDim  = dim3(1, 1, 1);
    cfg0.blockDim = dim3(1, 1, 1);
    cfg0.attrs = attrs;
    cfg0.numAttrs = 1;
    cudaLaunchKernelEx(&cfg0, init_out_kernel, out);

    // main kernel: PSS overlaps it with the init node; in-kernel GDS before
    // the atomicAdd enforces the only real dependency.
    cudaLaunchConfig_t cfg = {};
    cfg.gridDim  = dim3(NBLOCKS, 1, 1);
    cfg.blockDim = dim3(256, 1, 1);
    cfg.attrs = attrs;
    cfg.numAttrs = 1;
    cudaLaunchKernelEx(&cfg, nll_kernel, seq, sim, pers, w, out);
}

// round 14
// speedup vs baseline: 1.2140x; 1.0295x over previous
#include <cuda_runtime.h>
#include <cuda_bf16.h>
#include <cuda_fp16.h>
#include <math.h>

// Fixed shapes: seq (256,40) int32, sim (512,512) f32, pers (512,512,512) f32,
// weights (2,) f32, output scalar f32.
constexpr int V = 512;
constexpr int B = 256;
constexpr int L = 40;
constexpr int ROWS = B * (L - 1);        // 9984
constexpr int WARPS_PER_BLOCK = 8;       // 256 threads
constexpr int NBLOCKS = 624;             // 4992 warps x 2 rows = 9984 (one flat wave)
constexpr int TOTAL_WARPS = NBLOCKS * WARPS_PER_BLOCK;  // 4992

constexpr float LOG2E = 1.44269504088896340736f;
constexpr float LN2   = 0.69314718055994530942f;

// 32-byte global load with L2 evict_last (sm_103a ptxas requires .v8.b32).
struct F8 { float v[8]; };
__device__ __forceinline__ F8 ldg_el8(const float* p) {
    F8 r;
    asm("ld.global.nc.L2::evict_last.v8.b32 {%0,%1,%2,%3,%4,%5,%6,%7}, [%8];"
        : "=f"(r.v[0]), "=f"(r.v[1]), "=f"(r.v[2]), "=f"(r.v[3]),
          "=f"(r.v[4]), "=f"(r.v[5]), "=f"(r.v[6]), "=f"(r.v[7])
        : "l"(p));
    return r;
}

__device__ __forceinline__ void prefetch_l2(const void* p) {
    asm volatile("prefetch.global.L2 [%0];" :: "l"(p));
}

__global__ void init_out_kernel(float* out) {
    // Order against the PREVIOUS replay's nll_kernel atomics before overwrite.
    cudaGridDependencySynchronize();
    out[0] = (float)B * logf((float)V);  // nll0
    cudaTriggerProgrammaticLaunchCompletion();
}

__global__ __launch_bounds__(256)
void nll_kernel(const int* __restrict__ seq,
                const float* __restrict__ sim,
                const float* __restrict__ pers,
                const float* __restrict__ w,
                float* __restrict__ out) {
    const int warp = threadIdx.x >> 5;
    const int lane = threadIdx.x & 31;
    const int gw   = blockIdx.x * WARPS_PER_BLOCK + warp;   // 0..4991

    const float w0l = w[0] * LOG2E;
    const float w1l = w[1] * LOG2E;

    // Precompute both rows' indices/addresses.
    int   prevs[2], tgts[2];
    float w1s[2];
    const float* prows[2];
    #pragma unroll
    for (int k = 0; k < 2; k++) {
        const int row = gw + k * TOTAL_WARPS;
        const int b = row / (L - 1);
        const int t = row - b * (L - 1);
        const int base = b * L + t;
        const int prev = seq[base];
        prevs[k] = prev;
        tgts[k]  = seq[base + 1];
        const bool hasP = (t >= 1);
        const int p0 = hasP ? seq[base - 1] : prev;  // clamped, weight 0
        w1s[k] = hasP ? w1l : 0.f;
        prows[k] = pers + ((size_t)p0 * V + (size_t)prev) * V;
    }

    // Prefetch row 1's 2 KB pers block into L2 (16 lanes x 128 B), so its
    // DRAM activation overlaps row 0's compute. No registers held.
    if (lane < 16)
        prefetch_l2((const char*)prows[1] + lane * 128);

    float nll_acc = 0.f;
    #pragma unroll
    for (int k = 0; k < 2; k++) {
        const float w1r = w1s[k];

        // DRAM stream first: 2x v8 (64 B) per lane from the pers row.
        F8 pv[2];
        #pragma unroll
        for (int j = 0; j < 2; j++) pv[j] = ldg_el8(prows[k] + (lane + 32 * j) * 8);

        // L2-resident sim row.
        const float* srow = sim + (size_t)prevs[k] * V;
        F8 sv[2];
        #pragma unroll
        for (int j = 0; j < 2; j++) sv[j] = ldg_el8(srow + (lane + 32 * j) * 8);

        const int tgt = tgts[k];
        const int tj = tgt >> 8;
        const int tl = (tgt >> 3) & 31;
        const int tc = tgt & 7;

        float se = 0.f, tv = 0.f;
        #pragma unroll
        for (int j = 0; j < 2; j++) {
            float y[8];
            #pragma unroll
            for (int c = 0; c < 8; c++)
                y[c] = fmaf(w1r, pv[j].v[c], w0l * sv[j].v[c]);

            #pragma unroll
            for (int c = 0; c < 8; c += 4) {
                __half2 ea = h2exp2(__floats2half2_rn(y[c],     y[c + 1]));
                __half2 eb = h2exp2(__floats2half2_rn(y[c + 2], y[c + 3]));
                __half2 hs = __hadd2(ea, eb);
                float2 f = __half22float2(hs);
                se += f.x + f.y;
            }
            if (j == tj) tv = y[tc];
        }

        #pragma unroll
        for (int o = 16; o; o >>= 1) se += __shfl_xor_sync(0xffffffffu, se, o);
        tv = __shfl_sync(0xffffffffu, tv, tl);

        nll_acc += LN2 * (__log2f(se) - tv);   // identical across lanes
    }

    __shared__ float sh[WARPS_PER_BLOCK];
    if (lane == 0) sh[warp] = nll_acc;
    __syncthreads();

    if (threadIdx.x == 0) {
        float acc = 0.f;
        #pragma unroll
        for (int i = 0; i < WARPS_PER_BLOCK; i++) acc += sh[i];
        // PDL: init kernel's out[0] = nll0 store must be visible first.
        cudaGridDependencySynchronize();
        atomicAdd(out, acc);
    }
}

extern "C" void kernel_launch(void* const* d_in, const int* in_sizes, int n_in,
                              void* d_out, int out_size) {
    const int*   seq  = (const int*)  d_in[0];
    const float* sim  = (const float*)d_in[1];
    const float* pers = (const float*)d_in[2];
    const float* w    = (const float*)d_in[3];
    float* out = (float*)d_out;

    cudaLaunchAttribute attrs[1];
    attrs[0].id = cudaLaunchAttributeProgrammaticStreamSerialization;
    attrs[0].val.programmaticStreamSerializationAllowed = 1;

    cudaLaunchConfig_t cfg0 = {};
    cfg0.gridDim  = dim3(1, 1, 1);
    cfg0.blockDim = dim3(1, 1, 1);
    cfg0.attrs = attrs;
    cfg0.numAttrs = 1;
    cudaLaunchKernelEx(&cfg0, init_out_kernel, out);

    cudaLaunchConfig_t cfg = {};
    cfg.gridDim  = dim3(NBLOCKS, 1, 1);
    cfg.blockDim = dim3(256, 1, 1);
    cfg.attrs = attrs;
    cfg.numAttrs = 1;
    cudaLaunchKernelEx(&cfg, nll_kernel, seq, sim, pers, w, out);
}